// round 3
// baseline (speedup 1.0000x reference)
#include <cuda_runtime.h>
#include <math.h>
#include <stdint.h>

#define Bn 512
#define Tn 256
#define Cn 192
#define Hn 64
#define NROWS (Bn * Tn)

// Scratch (device globals = sanctioned alloc-free mechanism)
__device__ float g_q[(size_t)NROWS * Hn];        // [b*t][h] row-major
__device__ float g_kT[(size_t)Bn * Hn * Tn];     // [b][h][t] transposed
__device__ float g_vT[(size_t)Bn * Hn * Tn];     // [b][h][t] transposed
__device__ float g_pos[Tn * 128];                // [t][ pos_k | pos_q ]
__device__ float g_bias[Tn * Tn];

// ---------------------------------------------------------------------------
__device__ __forceinline__ unsigned f2tf(float f) {
    unsigned u;
    asm("cvt.rna.tf32.f32 %0, %1;" : "=r"(u) : "f"(f));
    return u;
}

__device__ __forceinline__ void mma_tf32(float c[4], const unsigned a[4],
                                         unsigned b0, unsigned b1) {
    asm volatile(
        "mma.sync.aligned.m16n8k8.row.col.f32.tf32.tf32.f32 "
        "{%0,%1,%2,%3}, {%4,%5,%6,%7}, {%8,%9}, {%0,%1,%2,%3};"
        : "+f"(c[0]), "+f"(c[1]), "+f"(c[2]), "+f"(c[3])
        : "r"(a[0]), "r"(a[1]), "r"(a[2]), "r"(a[3]), "r"(b0), "r"(b1));
}

// ---------------------------------------------------------------------------
// Kernel 1: QKV projection with tf32 mma, ZERO smem.
// 1024 CTAs x 256 thr, 2 CTAs/SM. Warp does a 16-row tile over K=192,
// all 64 out cols, all 3 weights. B-frags loaded straight from global
// (W is L1/L2 resident) with inline tf32 convert.
// ---------------------------------------------------------------------------
__global__ __launch_bounds__(256, 2) void qkv_mma_kernel(const float* __restrict__ x,
                                                         const float* __restrict__ Wq,
                                                         const float* __restrict__ Wk,
                                                         const float* __restrict__ Wv) {
    const int tid = threadIdx.x;
    const int w = tid >> 5, lane = tid & 31;
    const int gq = lane >> 2, tg = lane & 3;
    const int row0 = blockIdx.x * 128 + w * 16;
    const float* __restrict__ xb = x + (size_t)row0 * 192;

    float acc[3][8][4];
#pragma unroll
    for (int s = 0; s < 3; s++)
#pragma unroll
        for (int n = 0; n < 8; n++)
#pragma unroll
            for (int i = 0; i < 4; i++) acc[s][n][i] = 0.0f;

    unsigned a[4], an[4];
    a[0] = f2tf(xb[gq * 192 + tg]);
    a[1] = f2tf(xb[(gq + 8) * 192 + tg]);
    a[2] = f2tf(xb[gq * 192 + tg + 4]);
    a[3] = f2tf(xb[(gq + 8) * 192 + tg + 4]);

    for (int kk = 0; kk < 24; kk++) {
        if (kk < 23) {
            int kb = (kk + 1) * 8;
            an[0] = f2tf(xb[gq * 192 + kb + tg]);
            an[1] = f2tf(xb[(gq + 8) * 192 + kb + tg]);
            an[2] = f2tf(xb[gq * 192 + kb + tg + 4]);
            an[3] = f2tf(xb[(gq + 8) * 192 + kb + tg + 4]);
        }
        // B-frag base rows for this k-step
        const int r0w = (kk * 8 + tg) * 64 + gq;
        const int r1w = (kk * 8 + tg + 4) * 64 + gq;
#pragma unroll
        for (int sel = 0; sel < 3; sel++) {
            const float* __restrict__ W = (sel == 0) ? Wq : ((sel == 1) ? Wk : Wv);
#pragma unroll
            for (int nt = 0; nt < 8; nt++) {
                unsigned b0 = f2tf(W[r0w + nt * 8]);
                unsigned b1 = f2tf(W[r1w + nt * 8]);
                mma_tf32(acc[sel][nt], a, b0, b1);
            }
        }
        a[0] = an[0]; a[1] = an[1]; a[2] = an[2]; a[3] = an[3];
    }

    // Epilogue. q row-major; k,v transposed [b][h][t].
    const int bb = row0 >> 8;
    const int t0 = (row0 & 255) + gq;
    float* qout = g_q + (size_t)row0 * 64;
    float* kb_ = g_kT + (size_t)bb * 16384;
    float* vb_ = g_vT + (size_t)bb * 16384;
#pragma unroll
    for (int nt = 0; nt < 8; nt++) {
        int col = nt * 8 + 2 * tg;
        *(float2*)(qout + (size_t)gq * 64 + col) = make_float2(acc[0][nt][0], acc[0][nt][1]);
        *(float2*)(qout + (size_t)(gq + 8) * 64 + col) = make_float2(acc[0][nt][2], acc[0][nt][3]);
        kb_[col * 256 + t0]           = acc[1][nt][0];
        kb_[(col + 1) * 256 + t0]     = acc[1][nt][1];
        kb_[col * 256 + t0 + 8]       = acc[1][nt][2];
        kb_[(col + 1) * 256 + t0 + 8] = acc[1][nt][3];
        vb_[col * 256 + t0]           = acc[2][nt][0];
        vb_[(col + 1) * 256 + t0]     = acc[2][nt][1];
        vb_[col * 256 + t0 + 8]       = acc[2][nt][2];
        vb_[(col + 1) * 256 + t0 + 8] = acc[2][nt][3];
    }
}

// ---------------------------------------------------------------------------
// Kernel 2 + 3: positional projections and bias (tiny, fp32 exact)
// ---------------------------------------------------------------------------
__global__ __launch_bounds__(256) void pos_kernel(const float* __restrict__ pe,
                                                  const float* __restrict__ Wk,
                                                  const float* __restrict__ Wq) {
    int idx = blockIdx.x * 256 + threadIdx.x;
    int t = idx >> 7;
    int j = idx & 127;
    const float* __restrict__ W = (j < 64) ? Wk : Wq;
    int col = j & 63;
    float s = 0.0f;
#pragma unroll 4
    for (int c = 0; c < 192; c++) s = fmaf(pe[t * 192 + c], W[c * 64 + col], s);
    g_pos[idx] = s;
}

__global__ __launch_bounds__(256) void bias_kernel() {
    int i = blockIdx.x;
    int j = threadIdx.x;
    float s = 0.0f;
#pragma unroll 4
    for (int h = 0; h < 64; h++)
        s = fmaf(g_pos[i * 128 + h], g_pos[j * 128 + 64 + h], s);
    g_bias[i * 256 + j] = s;
}

// ---------------------------------------------------------------------------
// Kernel 4: flash attention with tf32 mma. One CTA per batch, 8 warps,
// 2 CTAs/SM (smem 77.8KB). K^T staged tf32 in smem (stride 264, conflict-free);
// V^T streamed from global with inline tf32 convert. Warp w handles q-tiles
// {w, 15-w} (balanced 17 j-tiles each).
// ---------------------------------------------------------------------------
#define KVS 264
__global__ __launch_bounds__(256, 2) void attn_mma_kernel(float* __restrict__ out) {
    extern __shared__ float sm[];
    float* k_s = sm;                       // [64][264]
    float* p_s = sm + 64 * KVS;            // [8][16][20]

    const int b = blockIdx.x;
    const int tid = threadIdx.x, w = tid >> 5, lane = tid & 31;
    const int gq = lane >> 2, tg = lane & 3;

    // Stage K^T (coalesced reads, conflict-free v4 stores), tf32-convert.
    const float* __restrict__ kg = g_kT + (size_t)b * 16384;
    const float* __restrict__ vg = g_vT + (size_t)b * 16384;
    for (int f = tid; f < 4096; f += 256) {
        int h = f >> 6, t4 = (f & 63) * 4;
        float4 kv = *(const float4*)(kg + h * 256 + t4);
        float* kd = k_s + h * KVS + t4;
        kd[0] = __uint_as_float(f2tf(kv.x));
        kd[1] = __uint_as_float(f2tf(kv.y));
        kd[2] = __uint_as_float(f2tf(kv.z));
        kd[3] = __uint_as_float(f2tf(kv.w));
    }
    __syncthreads();

    float* pw = p_s + w * 320;
    const float scale = rsqrtf(192.0f);

    for (int pass = 0; pass < 2; pass++) {
        const int qt = pass ? (15 - w) : w;
        const int r0 = qt * 16;

        // Q fragments for all 8 k-steps (held in registers)
        unsigned qa[8][4];
        const float* __restrict__ qg = g_q + ((size_t)b * 256 + r0) * 64;
#pragma unroll
        for (int kk = 0; kk < 8; kk++) {
            int c = kk * 8 + tg;
            qa[kk][0] = f2tf(qg[gq * 64 + c]);
            qa[kk][1] = f2tf(qg[(gq + 8) * 64 + c]);
            qa[kk][2] = f2tf(qg[gq * 64 + c + 4]);
            qa[kk][3] = f2tf(qg[(gq + 8) * 64 + c + 4]);
        }

        float o[8][4];
#pragma unroll
        for (int n = 0; n < 8; n++)
#pragma unroll
            for (int i = 0; i < 4; i++) o[n][i] = 0.0f;
        float m0 = -1e30f, m1 = -1e30f, l0 = 0.0f, l1 = 0.0f;

        for (int jt = 0; jt <= qt; jt++) {
            const int j0 = jt * 16;
            float s[2][4];
#pragma unroll
            for (int n = 0; n < 2; n++)
#pragma unroll
                for (int i = 0; i < 4; i++) s[n][i] = 0.0f;

            // S = Q K^T
#pragma unroll
            for (int kk = 0; kk < 8; kk++) {
                const float* kb2 = k_s + (kk * 8 + tg) * KVS + j0 + gq;
#pragma unroll
                for (int nt = 0; nt < 2; nt++) {
                    unsigned b0 = __float_as_uint(kb2[nt * 8]);
                    unsigned b1 = __float_as_uint(kb2[4 * KVS + nt * 8]);
                    mma_tf32(s[nt], qa[kk], b0, b1);
                }
            }

            // scale + bias + causal mask
            const int rowg = r0 + gq;
            const float* __restrict__ br0 = g_bias + rowg * 256 + j0;
            const float* __restrict__ br1 = br0 + 8 * 256;
#pragma unroll
            for (int nt = 0; nt < 2; nt++) {
                int c = nt * 8 + 2 * tg;
                float2 bias0 = *(const float2*)(br0 + c);
                float2 bias1 = *(const float2*)(br1 + c);
                s[nt][0] = fmaf(s[nt][0], scale, bias0.x);
                s[nt][1] = fmaf(s[nt][1], scale, bias0.y);
                s[nt][2] = fmaf(s[nt][2], scale, bias1.x);
                s[nt][3] = fmaf(s[nt][3], scale, bias1.y);
                if (jt == qt) {
                    int col = j0 + c;
                    if (col > rowg)         s[nt][0] = -1e30f;
                    if (col + 1 > rowg)     s[nt][1] = -1e30f;
                    if (col > rowg + 8)     s[nt][2] = -1e30f;
                    if (col + 1 > rowg + 8) s[nt][3] = -1e30f;
                }
            }

            // online softmax update
            float mx0 = fmaxf(fmaxf(s[0][0], s[0][1]), fmaxf(s[1][0], s[1][1]));
            float mx1 = fmaxf(fmaxf(s[0][2], s[0][3]), fmaxf(s[1][2], s[1][3]));
            mx0 = fmaxf(mx0, __shfl_xor_sync(0xffffffffu, mx0, 1));
            mx0 = fmaxf(mx0, __shfl_xor_sync(0xffffffffu, mx0, 2));
            mx1 = fmaxf(mx1, __shfl_xor_sync(0xffffffffu, mx1, 1));
            mx1 = fmaxf(mx1, __shfl_xor_sync(0xffffffffu, mx1, 2));
            float mn0 = fmaxf(m0, mx0), mn1 = fmaxf(m1, mx1);
            float al0 = __expf(m0 - mn0), al1 = __expf(m1 - mn1);
            m0 = mn0; m1 = mn1;

            float e00 = __expf(s[0][0] - mn0), e01 = __expf(s[0][1] - mn0);
            float e10 = __expf(s[1][0] - mn0), e11 = __expf(s[1][1] - mn0);
            float e02 = __expf(s[0][2] - mn1), e03 = __expf(s[0][3] - mn1);
            float e12 = __expf(s[1][2] - mn1), e13 = __expf(s[1][3] - mn1);

            float sum0 = (e00 + e01) + (e10 + e11);
            float sum1 = (e02 + e03) + (e12 + e13);
            sum0 += __shfl_xor_sync(0xffffffffu, sum0, 1);
            sum0 += __shfl_xor_sync(0xffffffffu, sum0, 2);
            sum1 += __shfl_xor_sync(0xffffffffu, sum1, 1);
            sum1 += __shfl_xor_sync(0xffffffffu, sum1, 2);
            l0 = l0 * al0 + sum0;
            l1 = l1 * al1 + sum1;

#pragma unroll
            for (int nt = 0; nt < 8; nt++) {
                o[nt][0] *= al0; o[nt][1] *= al0;
                o[nt][2] *= al1; o[nt][3] *= al1;
            }

            // stage P (tf32) to per-warp smem, stride 20 (conflict-free A-frags)
            *(float2*)(pw + gq * 20 + 2 * tg) =
                make_float2(__uint_as_float(f2tf(e00)), __uint_as_float(f2tf(e01)));
            *(float2*)(pw + gq * 20 + 8 + 2 * tg) =
                make_float2(__uint_as_float(f2tf(e10)), __uint_as_float(f2tf(e11)));
            *(float2*)(pw + (gq + 8) * 20 + 2 * tg) =
                make_float2(__uint_as_float(f2tf(e02)), __uint_as_float(f2tf(e03)));
            *(float2*)(pw + (gq + 8) * 20 + 8 + 2 * tg) =
                make_float2(__uint_as_float(f2tf(e12)), __uint_as_float(f2tf(e13)));
            __syncwarp();

            // O += P V   (V streamed from global, tf32 convert inline)
#pragma unroll
            for (int ks = 0; ks < 2; ks++) {
                unsigned pa[4];
                pa[0] = __float_as_uint(pw[gq * 20 + ks * 8 + tg]);
                pa[1] = __float_as_uint(pw[(gq + 8) * 20 + ks * 8 + tg]);
                pa[2] = __float_as_uint(pw[gq * 20 + ks * 8 + tg + 4]);
                pa[3] = __float_as_uint(pw[(gq + 8) * 20 + ks * 8 + tg + 4]);
#pragma unroll
                for (int nt = 0; nt < 8; nt++) {
                    const float* __restrict__ vb2 =
                        vg + (nt * 8 + gq) * 256 + j0 + ks * 8 + tg;
                    unsigned b0 = f2tf(vb2[0]);
                    unsigned b1 = f2tf(vb2[4]);
                    mma_tf32(o[nt], pa, b0, b1);
                }
            }
            __syncwarp();
        }

        float inv0 = 1.0f / l0, inv1 = 1.0f / l1;
        float* ob = out + ((size_t)b * 256 + r0) * 64;
#pragma unroll
        for (int nt = 0; nt < 8; nt++) {
            int c = nt * 8 + 2 * tg;
            *(float2*)(ob + gq * 64 + c) = make_float2(o[nt][0] * inv0, o[nt][1] * inv0);
            *(float2*)(ob + (gq + 8) * 64 + c) = make_float2(o[nt][2] * inv1, o[nt][3] * inv1);
        }
    }
}

// ---------------------------------------------------------------------------
extern "C" void kernel_launch(void* const* d_in, const int* in_sizes, int n_in,
                              void* d_out, int out_size) {
    const float* x  = (const float*)d_in[0];
    const float* Wk = (const float*)d_in[1];
    const float* Wq = (const float*)d_in[2];
    const float* Wv = (const float*)d_in[3];
    const float* pe = (const float*)d_in[4];
    float* out = (float*)d_out;
    (void)in_sizes; (void)n_in; (void)out_size;

    static bool attr_set = false;
    if (!attr_set) {
        cudaFuncSetAttribute(attn_mma_kernel,
                             cudaFuncAttributeMaxDynamicSharedMemorySize, 77824);
        attr_set = true;
    }

    qkv_mma_kernel<<<1024, 256>>>(x, Wq, Wk, Wv);
    pos_kernel<<<128, 256>>>(pe, Wk, Wq);
    bias_kernel<<<256, 256>>>();
    attn_mma_kernel<<<512, 256, 77824>>>(out);
}

// round 5
// speedup vs baseline: 2.0150x; 2.0150x over previous
#include <cuda_runtime.h>
#include <math.h>
#include <stdint.h>

#define Bn 512
#define Tn 256
#define Cn 192
#define Hn 64
#define NROWS (Bn * Tn)

// Scratch (device globals = sanctioned alloc-free mechanism)
__device__ float g_q[(size_t)NROWS * Hn];        // [b*t][h], pre-scaled, tf32-rounded
__device__ float g_kT[(size_t)Bn * Hn * Tn];     // [b][h][t], tf32-rounded
__device__ float g_vT[(size_t)Bn * Hn * Tn];     // [b][h][t], tf32-rounded
__device__ float g_pos[Tn * 128];                // [t][ pos_k | pos_q ]  fp32
__device__ float g_bias[Tn * Tn];                // fp32 exact

// ---------------------------------------------------------------------------
__device__ __forceinline__ unsigned f2tf(float f) {
    unsigned u;
    asm("cvt.rna.tf32.f32 %0, %1;" : "=r"(u) : "f"(f));
    return u;
}
__device__ __forceinline__ float f2tff(float f) { return __uint_as_float(f2tf(f)); }

__device__ __forceinline__ void mma_tf32(float c[4], const unsigned a[4],
                                         unsigned b0, unsigned b1) {
    asm volatile(
        "mma.sync.aligned.m16n8k8.row.col.f32.tf32.tf32.f32 "
        "{%0,%1,%2,%3}, {%4,%5,%6,%7}, {%8,%9}, {%0,%1,%2,%3};"
        : "+f"(c[0]), "+f"(c[1]), "+f"(c[2]), "+f"(c[3])
        : "r"(a[0]), "r"(a[1]), "r"(a[2]), "r"(a[3]), "r"(b0), "r"(b1));
}

__device__ __forceinline__ unsigned smaddr(const void* p) {
    return (unsigned)__cvta_generic_to_shared(p);
}
#define CP_ASYNC16(dst, src) \
    asm volatile("cp.async.ca.shared.global [%0], [%1], 16;" :: "r"(dst), "l"(src))
#define CP_COMMIT() asm volatile("cp.async.commit_group;")
#define CP_WAIT0()  asm volatile("cp.async.wait_group 0;")

// ---------------------------------------------------------------------------
// Kernel 1: QKV projection, split by output matrix. grid (3, 1024):
// blockIdx.x = sel (fastest-varying -> x tiles L2-shared across sels),
// blockIdx.y = 128-row tile. One W [192][72] tf32 in smem (55.3KB, stride 72:
// 72 mod 32 = 8 -> B-frag banks 8tg+8nt+gq all distinct). Outputs tf32-rounded,
// q pre-scaled by C^-0.5.
// ---------------------------------------------------------------------------
#define WS 72
__global__ __launch_bounds__(256) void qkv_mma_kernel(const float* __restrict__ x,
                                                      const float* __restrict__ Wq,
                                                      const float* __restrict__ Wk,
                                                      const float* __restrict__ Wv) {
    extern __shared__ float W_s[];   // [192][72]
    const int sel = blockIdx.x;
    const int tid = threadIdx.x;
    const float* __restrict__ W = (sel == 0) ? Wq : ((sel == 1) ? Wk : Wv);

    for (int f = tid; f < 3072; f += 256) {          // 192*16 float4
        int k = f >> 4, n4 = f & 15;
        float4 v = *(const float4*)(W + k * 64 + n4 * 4);
        float* d = W_s + k * WS + n4 * 4;
        d[0] = f2tff(v.x); d[1] = f2tff(v.y); d[2] = f2tff(v.z); d[3] = f2tff(v.w);
    }
    __syncthreads();

    const int w = tid >> 5, lane = tid & 31;
    const int gq = lane >> 2, tg = lane & 3;
    const int row0 = blockIdx.y * 128 + w * 16;
    const float* __restrict__ xb = x + (size_t)row0 * 192;

    float acc[8][4];
#pragma unroll
    for (int n = 0; n < 8; n++)
#pragma unroll
        for (int i = 0; i < 4; i++) acc[n][i] = 0.0f;

    unsigned a[4], an[4];
    a[0] = f2tf(xb[gq * 192 + tg]);
    a[1] = f2tf(xb[(gq + 8) * 192 + tg]);
    a[2] = f2tf(xb[gq * 192 + tg + 4]);
    a[3] = f2tf(xb[(gq + 8) * 192 + tg + 4]);

    for (int kk = 0; kk < 24; kk++) {
        if (kk < 23) {
            int kb = (kk + 1) * 8;
            an[0] = f2tf(xb[gq * 192 + kb + tg]);
            an[1] = f2tf(xb[(gq + 8) * 192 + kb + tg]);
            an[2] = f2tf(xb[gq * 192 + kb + tg + 4]);
            an[3] = f2tf(xb[(gq + 8) * 192 + kb + tg + 4]);
        }
        const float* wb = W_s + (kk * 8 + tg) * WS + gq;
#pragma unroll
        for (int nt = 0; nt < 8; nt++) {
            unsigned b0 = __float_as_uint(wb[nt * 8]);
            unsigned b1 = __float_as_uint(wb[4 * WS + nt * 8]);
            mma_tf32(acc[nt], a, b0, b1);
        }
        a[0] = an[0]; a[1] = an[1]; a[2] = an[2]; a[3] = an[3];
    }

    const int bb = row0 >> 8;
    const int t0 = (row0 & 255) + gq;
    if (sel == 0) {
        const float scale = rsqrtf(192.0f);
        float* qout = g_q + (size_t)row0 * 64;
#pragma unroll
        for (int nt = 0; nt < 8; nt++) {
            int col = nt * 8 + 2 * tg;
            *(float2*)(qout + (size_t)gq * 64 + col) =
                make_float2(f2tff(acc[nt][0] * scale), f2tff(acc[nt][1] * scale));
            *(float2*)(qout + (size_t)(gq + 8) * 64 + col) =
                make_float2(f2tff(acc[nt][2] * scale), f2tff(acc[nt][3] * scale));
        }
    } else {
        float* ob = ((sel == 1) ? g_kT : g_vT) + (size_t)bb * 16384;
#pragma unroll
        for (int nt = 0; nt < 8; nt++) {
            int col = nt * 8 + 2 * tg;
            ob[col * 256 + t0]           = f2tff(acc[nt][0]);
            ob[(col + 1) * 256 + t0]     = f2tff(acc[nt][1]);
            ob[col * 256 + t0 + 8]       = f2tff(acc[nt][2]);
            ob[(col + 1) * 256 + t0 + 8] = f2tff(acc[nt][3]);
        }
    }
}

// ---------------------------------------------------------------------------
// Kernel 2 + 3: positional projections and bias (tiny, fp32 exact)
// ---------------------------------------------------------------------------
__global__ __launch_bounds__(256) void pos_kernel(const float* __restrict__ pe,
                                                  const float* __restrict__ Wk,
                                                  const float* __restrict__ Wq) {
    int idx = blockIdx.x * 256 + threadIdx.x;
    int t = idx >> 7;
    int j = idx & 127;
    const float* __restrict__ W = (j < 64) ? Wk : Wq;
    int col = j & 63;
    float s = 0.0f;
#pragma unroll 4
    for (int c = 0; c < 192; c++) s = fmaf(pe[t * 192 + c], W[c * 64 + col], s);
    g_pos[idx] = s;
}

__global__ __launch_bounds__(256) void bias_kernel() {
    int i = blockIdx.x;
    int j = threadIdx.x;
    float s = 0.0f;
#pragma unroll 4
    for (int h = 0; h < 64; h++)
        s = fmaf(g_pos[i * 128 + h], g_pos[j * 128 + 64 + h], s);
    g_bias[i * 256 + j] = s;
}

// ---------------------------------------------------------------------------
// Kernel 4: flash-block attention. CTA = 128 q-rows (grid 2 x 512), 8 warps.
// Warp w owns interleaved rows qb*128 + fr*8 + w (fr=0..15) for causal balance.
// j-tiles of 32 cols; K tile (stride 40) + V tile (stride 36) cp.async
// double-buffered. All operands pre-tf32. 57KB smem, 2 CTAs/SM.
// ---------------------------------------------------------------------------
#define KS 40
#define VS 36
#define PS 36
__global__ __launch_bounds__(256, 2) void attn_mma_kernel(float* __restrict__ out) {
    extern __shared__ float sm[];
    float* kbuf[2] = { sm, sm + 2560 };                       // 64 x 40 each
    float* vbuf[2] = { sm + 5120, sm + 5120 + 2304 };         // 64 x 36 each
    float* p_s = sm + 5120 + 4608;                            // 8 x 16 x 36

    const int qb = blockIdx.x;        // 0 or 1
    const int b  = blockIdx.y;
    const int tid = threadIdx.x, w = tid >> 5, lane = tid & 31;
    const int gq = lane >> 2, tg = lane & 3;
    const int nj = (qb + 1) * 4;

    const float* __restrict__ kg = g_kT + (size_t)b * 16384;
    const float* __restrict__ vg = g_vT + (size_t)b * 16384;

    // Q fragments (virtual row gq -> actual qb*128 + gq*8 + w; gq+8 -> +64)
    const int rowg = qb * 128 + gq * 8 + w;
    const int row2 = rowg + 64;
    unsigned qa[8][4];
    {
        const float* __restrict__ qg = g_q + ((size_t)b * 256 + qb * 128) * 64;
        const int r0 = gq * 8 + w, r1 = r0 + 64;
#pragma unroll
        for (int kk = 0; kk < 8; kk++) {
            int c = kk * 8 + tg;
            qa[kk][0] = __float_as_uint(qg[r0 * 64 + c]);
            qa[kk][1] = __float_as_uint(qg[r1 * 64 + c]);
            qa[kk][2] = __float_as_uint(qg[r0 * 64 + c + 4]);
            qa[kk][3] = __float_as_uint(qg[r1 * 64 + c + 4]);
        }
    }

    float o[8][4];
#pragma unroll
    for (int n = 0; n < 8; n++)
#pragma unroll
        for (int i = 0; i < 4; i++) o[n][i] = 0.0f;
    float m0 = -1e30f, m1 = -1e30f, l0 = 0.0f, l1 = 0.0f;

    float* pw = p_s + w * 576;

    // Prologue: stage tile 0 into buffer 0
    for (int f = tid; f < 512; f += 256) {
        int h = f >> 3, c4 = (f & 7) * 4;
        CP_ASYNC16(smaddr(kbuf[0] + h * KS + c4), kg + h * 256 + c4);
        CP_ASYNC16(smaddr(vbuf[0] + h * VS + c4), vg + h * 256 + c4);
    }
    CP_COMMIT();

    int buf = 0;
    for (int jt = 0; jt < nj; jt++) {
        const int j0 = jt * 32;
        CP_WAIT0();
        __syncthreads();

        if (jt + 1 < nj) {
            const int jn = j0 + 32;
            float* kn = kbuf[buf ^ 1];
            float* vn = vbuf[buf ^ 1];
            for (int f = tid; f < 512; f += 256) {
                int h = f >> 3, c4 = (f & 7) * 4;
                CP_ASYNC16(smaddr(kn + h * KS + c4), kg + h * 256 + jn + c4);
                CP_ASYNC16(smaddr(vn + h * VS + c4), vg + h * 256 + jn + c4);
            }
            CP_COMMIT();
        }

        const float* kb = kbuf[buf];
        const float* vb = vbuf[buf];

        // S = Q K^T  (q pre-scaled)
        float s[4][4];
#pragma unroll
        for (int n = 0; n < 4; n++)
#pragma unroll
            for (int i = 0; i < 4; i++) s[n][i] = 0.0f;
#pragma unroll
        for (int kk = 0; kk < 8; kk++) {
            const float* kb2 = kb + (kk * 8 + tg) * KS + gq;
#pragma unroll
            for (int nt = 0; nt < 4; nt++) {
                unsigned b0 = __float_as_uint(kb2[nt * 8]);
                unsigned b1 = __float_as_uint(kb2[4 * KS + nt * 8]);
                mma_tf32(s[nt], qa[kk], b0, b1);
            }
        }

        // + bias (fp32 from global), causal mask
        const float* __restrict__ br0 = g_bias + (size_t)rowg * 256 + j0;
        const float* __restrict__ br1 = g_bias + (size_t)row2 * 256 + j0;
#pragma unroll
        for (int nt = 0; nt < 4; nt++) {
            int c = nt * 8 + 2 * tg;
            int col = j0 + c;
            float2 bias0 = *(const float2*)(br0 + c);
            float2 bias1 = *(const float2*)(br1 + c);
            s[nt][0] = (col     <= rowg) ? (s[nt][0] + bias0.x) : -1e30f;
            s[nt][1] = (col + 1 <= rowg) ? (s[nt][1] + bias0.y) : -1e30f;
            s[nt][2] = (col     <= row2) ? (s[nt][2] + bias1.x) : -1e30f;
            s[nt][3] = (col + 1 <= row2) ? (s[nt][3] + bias1.y) : -1e30f;
        }

        // online softmax
        float mx0 = -1e30f, mx1 = -1e30f;
#pragma unroll
        for (int nt = 0; nt < 4; nt++) {
            mx0 = fmaxf(mx0, fmaxf(s[nt][0], s[nt][1]));
            mx1 = fmaxf(mx1, fmaxf(s[nt][2], s[nt][3]));
        }
        mx0 = fmaxf(mx0, __shfl_xor_sync(0xffffffffu, mx0, 1));
        mx0 = fmaxf(mx0, __shfl_xor_sync(0xffffffffu, mx0, 2));
        mx1 = fmaxf(mx1, __shfl_xor_sync(0xffffffffu, mx1, 1));
        mx1 = fmaxf(mx1, __shfl_xor_sync(0xffffffffu, mx1, 2));
        float mn0 = fmaxf(m0, mx0), mn1 = fmaxf(m1, mx1);
        float al0 = __expf(m0 - mn0), al1 = __expf(m1 - mn1);
        m0 = mn0; m1 = mn1;

        float sum0 = 0.0f, sum1 = 0.0f;
        float e[4][4];
#pragma unroll
        for (int nt = 0; nt < 4; nt++) {
            e[nt][0] = __expf(s[nt][0] - mn0);
            e[nt][1] = __expf(s[nt][1] - mn0);
            e[nt][2] = __expf(s[nt][2] - mn1);
            e[nt][3] = __expf(s[nt][3] - mn1);
            sum0 += e[nt][0] + e[nt][1];
            sum1 += e[nt][2] + e[nt][3];
        }
        sum0 += __shfl_xor_sync(0xffffffffu, sum0, 1);
        sum0 += __shfl_xor_sync(0xffffffffu, sum0, 2);
        sum1 += __shfl_xor_sync(0xffffffffu, sum1, 1);
        sum1 += __shfl_xor_sync(0xffffffffu, sum1, 2);
        l0 = l0 * al0 + sum0;
        l1 = l1 * al1 + sum1;

#pragma unroll
        for (int nt = 0; nt < 8; nt++) {
            o[nt][0] *= al0; o[nt][1] *= al0;
            o[nt][2] *= al1; o[nt][3] *= al1;
        }

        // stage P (tf32) per-warp, stride 36
#pragma unroll
        for (int nt = 0; nt < 4; nt++) {
            int c = nt * 8 + 2 * tg;
            *(float2*)(pw + gq * PS + c) =
                make_float2(f2tff(e[nt][0]), f2tff(e[nt][1]));
            *(float2*)(pw + (gq + 8) * PS + c) =
                make_float2(f2tff(e[nt][2]), f2tff(e[nt][3]));
        }
        __syncwarp();

        // O += P V
#pragma unroll
        for (int ks = 0; ks < 4; ks++) {
            unsigned pa[4];
            pa[0] = __float_as_uint(pw[gq * PS + ks * 8 + tg]);
            pa[1] = __float_as_uint(pw[(gq + 8) * PS + ks * 8 + tg]);
            pa[2] = __float_as_uint(pw[gq * PS + ks * 8 + tg + 4]);
            pa[3] = __float_as_uint(pw[(gq + 8) * PS + ks * 8 + tg + 4]);
#pragma unroll
            for (int nt = 0; nt < 8; nt++) {
                const float* vb2 = vb + (nt * 8 + gq) * VS + ks * 8 + tg;
                unsigned b0 = __float_as_uint(vb2[0]);
                unsigned b1 = __float_as_uint(vb2[4]);
                mma_tf32(o[nt], pa, b0, b1);
            }
        }
        __syncwarp();

        __syncthreads();      // all warps done reading buf before restage
        buf ^= 1;
    }

    float inv0 = 1.0f / l0, inv1 = 1.0f / l1;
    float* ob = out + ((size_t)b * 256) * 64;
    const int r0o = qb * 128 + gq * 8 + w;
#pragma unroll
    for (int nt = 0; nt < 8; nt++) {
        int c = nt * 8 + 2 * tg;
        *(float2*)(ob + (size_t)r0o * 64 + c) =
            make_float2(o[nt][0] * inv0, o[nt][1] * inv0);
        *(float2*)(ob + (size_t)(r0o + 64) * 64 + c) =
            make_float2(o[nt][2] * inv1, o[nt][3] * inv1);
    }
}

// ---------------------------------------------------------------------------
extern "C" void kernel_launch(void* const* d_in, const int* in_sizes, int n_in,
                              void* d_out, int out_size) {
    const float* x  = (const float*)d_in[0];
    const float* Wk = (const float*)d_in[1];
    const float* Wq = (const float*)d_in[2];
    const float* Wv = (const float*)d_in[3];
    const float* pe = (const float*)d_in[4];
    float* out = (float*)d_out;
    (void)in_sizes; (void)n_in; (void)out_size;

    static bool attr_set = false;
    if (!attr_set) {
        cudaFuncSetAttribute(qkv_mma_kernel,
                             cudaFuncAttributeMaxDynamicSharedMemorySize, 55296);
        cudaFuncSetAttribute(attn_mma_kernel,
                             cudaFuncAttributeMaxDynamicSharedMemorySize, 57344);
        attr_set = true;
    }

    qkv_mma_kernel<<<dim3(3, 1024), 256, 55296>>>(x, Wq, Wk, Wv);
    pos_kernel<<<128, 256>>>(pe, Wk, Wq);
    bias_kernel<<<256, 256>>>();
    attn_mma_kernel<<<dim3(2, 512), 256, 57344>>>(out);
}

// round 6
// speedup vs baseline: 2.0974x; 1.0409x over previous
#include <cuda_runtime.h>
#include <math.h>
#include <stdint.h>

#define Bn 512
#define Tn 256
#define Cn 192
#define Hn 64

// Scratch (device globals = sanctioned alloc-free mechanism)
__device__ float g_qF[(size_t)Bn * 2 * 8 * 1024];  // frag-major q (tf32, pre-scaled)
__device__ float g_kT[(size_t)Bn * Hn * Tn];       // [b][h][t], tf32-rounded
__device__ float g_vT[(size_t)Bn * Hn * Tn];       // [b][h][t], tf32-rounded
__device__ float g_pos[Tn * 128];                  // [t][ pos_k | pos_q ]  fp32
__device__ float g_biasF[12 * 8 * 32 * 16];        // frag-major bias, fp32 exact

// ---------------------------------------------------------------------------
__device__ __forceinline__ unsigned f2tf(float f) {
    unsigned u;
    asm("cvt.rna.tf32.f32 %0, %1;" : "=r"(u) : "f"(f));
    return u;
}
__device__ __forceinline__ float f2tff(float f) { return __uint_as_float(f2tf(f)); }

__device__ __forceinline__ void mma_tf32(float c[4], const unsigned a[4],
                                         unsigned b0, unsigned b1) {
    asm volatile(
        "mma.sync.aligned.m16n8k8.row.col.f32.tf32.tf32.f32 "
        "{%0,%1,%2,%3}, {%4,%5,%6,%7}, {%8,%9}, {%0,%1,%2,%3};"
        : "+f"(c[0]), "+f"(c[1]), "+f"(c[2]), "+f"(c[3])
        : "r"(a[0]), "r"(a[1]), "r"(a[2]), "r"(a[3]), "r"(b0), "r"(b1));
}

__device__ __forceinline__ unsigned smaddr(const void* p) {
    return (unsigned)__cvta_generic_to_shared(p);
}
#define CP_ASYNC16(dst, src) \
    asm volatile("cp.async.ca.shared.global [%0], [%1], 16;" :: "r"(dst), "l"(src))
#define CP_COMMIT() asm volatile("cp.async.commit_group;")

// ---------------------------------------------------------------------------
// Kernel 1: QKV projection. grid (3, 512): blockIdx.x = sel, blockIdx.y = b
// (256 rows). Warp tile 32x64 (B-frag reuse 2x). W [192][72] tf32 in smem;
// x chunks [256][20] cp.async double-buffered (20 mod 32 = 20: banks gq*20+tg
// all distinct). 96.3KB smem -> 2 CTAs/SM.
// ---------------------------------------------------------------------------
#define WS 72
#define XS 20
__global__ __launch_bounds__(256, 2) void qkv_mma_kernel(const float* __restrict__ x,
                                                         const float* __restrict__ Wq,
                                                         const float* __restrict__ Wk,
                                                         const float* __restrict__ Wv) {
    extern __shared__ float sm[];
    float* W_s = sm;                                   // 13824
    float* bufs[2] = { sm + 13824, sm + 13824 + 5120 };// 5120 each

    const int sel = blockIdx.x;
    const int tid = threadIdx.x;
    const float* __restrict__ W = (sel == 0) ? Wq : ((sel == 1) ? Wk : Wv);
    const float* __restrict__ xc = x + (size_t)blockIdx.y * 256 * 192;

    // prologue: chunk 0 (k 0..15, 256 rows)
    for (int f = tid; f < 1024; f += 256) {
        int r = f >> 2, f4 = f & 3;
        CP_ASYNC16(smaddr(bufs[0] + r * XS + f4 * 4), xc + r * 192 + f4 * 4);
    }
    CP_COMMIT();

    // stage W (tf32)
    for (int f = tid; f < 3072; f += 256) {
        int k = f >> 4, n4 = f & 15;
        float4 v = *(const float4*)(W + k * 64 + n4 * 4);
        float* d = W_s + k * WS + n4 * 4;
        d[0] = f2tff(v.x); d[1] = f2tff(v.y); d[2] = f2tff(v.z); d[3] = f2tff(v.w);
    }

    const int w = tid >> 5, lane = tid & 31;
    const int gq = lane >> 2, tg = lane & 3;

    float acc[2][8][4];
#pragma unroll
    for (int r = 0; r < 2; r++)
#pragma unroll
        for (int n = 0; n < 8; n++)
#pragma unroll
            for (int i = 0; i < 4; i++) acc[r][n][i] = 0.0f;

    int buf = 0;
    for (int c = 0; c < 12; c++) {
        if (c < 11) {
            const float* src = xc + (c + 1) * 16;
            float* dst = bufs[buf ^ 1];
            for (int f = tid; f < 1024; f += 256) {
                int r = f >> 2, f4 = f & 3;
                CP_ASYNC16(smaddr(dst + r * XS + f4 * 4), src + r * 192 + f4 * 4);
            }
            CP_COMMIT();
            asm volatile("cp.async.wait_group 1;");
        } else {
            asm volatile("cp.async.wait_group 0;");
        }
        __syncthreads();

        const float* xs = bufs[buf] + (w * 32) * XS;
#pragma unroll
        for (int ks = 0; ks < 16; ks += 8) {
            unsigned a0[4], a1[4];
            a0[0] = f2tf(xs[gq * XS + ks + tg]);
            a0[1] = f2tf(xs[(gq + 8) * XS + ks + tg]);
            a0[2] = f2tf(xs[gq * XS + ks + tg + 4]);
            a0[3] = f2tf(xs[(gq + 8) * XS + ks + tg + 4]);
            a1[0] = f2tf(xs[(gq + 16) * XS + ks + tg]);
            a1[1] = f2tf(xs[(gq + 24) * XS + ks + tg]);
            a1[2] = f2tf(xs[(gq + 16) * XS + ks + tg + 4]);
            a1[3] = f2tf(xs[(gq + 24) * XS + ks + tg + 4]);
            const float* wb = W_s + (c * 16 + ks + tg) * WS + gq;
#pragma unroll
            for (int nt = 0; nt < 8; nt++) {
                unsigned b0 = __float_as_uint(wb[nt * 8]);
                unsigned b1 = __float_as_uint(wb[4 * WS + nt * 8]);
                mma_tf32(acc[0][nt], a0, b0, b1);
                mma_tf32(acc[1][nt], a1, b0, b1);
            }
        }
        __syncthreads();
        buf ^= 1;
    }

    const int b = blockIdx.y;
    if (sel == 0) {
        // q -> frag-major g_qF (pre-scaled, tf32)
        const float scale = rsqrtf(192.0f);
        const int qb = w >> 2;
        float* qf = g_qF + (((size_t)b * 2 + qb) * 8 + gq) * 1024;
        const int tg0 = (2 * tg) & 3, tg1 = (2 * tg + 1) & 3, hi = tg >> 1;
#pragma unroll
        for (int r = 0; r < 2; r++) {
            int u = (w & 3) * 2 + r;
            int half = u >> 2, base8 = (u & 3) * 8;
            int e0 = hi * 2 + half;
#pragma unroll
            for (int nt = 0; nt < 8; nt++) {
                qf[(base8 + tg0) * 32 + nt * 4 + e0]     = f2tff(acc[r][nt][0] * scale);
                qf[(base8 + tg1) * 32 + nt * 4 + e0]     = f2tff(acc[r][nt][1] * scale);
                qf[(base8 + 4 + tg0) * 32 + nt * 4 + e0] = f2tff(acc[r][nt][2] * scale);
                qf[(base8 + 4 + tg1) * 32 + nt * 4 + e0] = f2tff(acc[r][nt][3] * scale);
            }
        }
    } else {
        float* ob = ((sel == 1) ? g_kT : g_vT) + (size_t)b * 16384;
#pragma unroll
        for (int r = 0; r < 2; r++) {
            int t0 = w * 32 + r * 16 + gq;
#pragma unroll
            for (int nt = 0; nt < 8; nt++) {
                int col = nt * 8 + 2 * tg;
                ob[col * 256 + t0]           = f2tff(acc[r][nt][0]);
                ob[(col + 1) * 256 + t0]     = f2tff(acc[r][nt][1]);
                ob[col * 256 + t0 + 8]       = f2tff(acc[r][nt][2]);
                ob[(col + 1) * 256 + t0 + 8] = f2tff(acc[r][nt][3]);
            }
        }
    }
}

// ---------------------------------------------------------------------------
// Kernel 2: positional projections (tiny, fp32 exact)
// ---------------------------------------------------------------------------
__global__ __launch_bounds__(256) void pos_kernel(const float* __restrict__ pe,
                                                  const float* __restrict__ Wk,
                                                  const float* __restrict__ Wq) {
    int idx = blockIdx.x * 256 + threadIdx.x;
    int t = idx >> 7;
    int j = idx & 127;
    const float* __restrict__ W = (j < 64) ? Wk : Wq;
    int col = j & 63;
    float s = 0.0f;
#pragma unroll 4
    for (int c = 0; c < 192; c++) s = fmaf(pe[t * 192 + c], W[c * 64 + col], s);
    g_pos[idx] = s;
}

// ---------------------------------------------------------------------------
// Kernel 3: bias in fragment-major layout (fp32 exact dots of g_pos).
// grid 12 (tiles: qb0 jt0-3 -> ti 0-3, qb1 jt0-7 -> ti 4-11), block (32,8).
// ---------------------------------------------------------------------------
__global__ void bias_frag_kernel() {
    const int ti = blockIdx.x;
    const int w = threadIdx.y, lane = threadIdx.x;
    const int gq = lane >> 2, tg = lane & 3;
    const int qb = (ti >= 4) ? 1 : 0;
    const int jt = qb ? (ti - 4) : ti;
    const int rowg = qb * 128 + gq * 8 + w;
    const int row2 = rowg + 64;
    float* o = g_biasF + ((size_t)(ti * 8 + w) * 32 + lane) * 16;
    const float* __restrict__ pk0 = g_pos + rowg * 128;
    const float* __restrict__ pk1 = g_pos + row2 * 128;
#pragma unroll
    for (int nt = 0; nt < 4; nt++) {
        int c0 = jt * 32 + nt * 8 + 2 * tg;
        const float* __restrict__ pq0 = g_pos + c0 * 128 + 64;
        const float* __restrict__ pq1 = pq0 + 128;
        float d00 = 0.f, d01 = 0.f, d10 = 0.f, d11 = 0.f;
#pragma unroll 4
        for (int h = 0; h < 64; h++) {
            float a0 = pk0[h], a1 = pk1[h];
            float b0v = pq0[h], b1v = pq1[h];
            d00 = fmaf(a0, b0v, d00); d01 = fmaf(a0, b1v, d01);
            d10 = fmaf(a1, b0v, d10); d11 = fmaf(a1, b1v, d11);
        }
        *(float4*)(o + nt * 4) = make_float4(d00, d01, d10, d11);
    }
}

// ---------------------------------------------------------------------------
// Kernel 4: flash-block attention. CTA = 128 q-rows (grid 2 x 512), 8 warps.
// Warp w owns rows qb*128 + gq*8 + w (+64). j-tiles of 32; K (stride 40) +
// V (stride 36) cp.async double-buffered. Bias + Q read frag-major coalesced.
// 57KB smem, 2 CTAs/SM.
// ---------------------------------------------------------------------------
#define KS 40
#define VS 36
#define PS 36
__global__ __launch_bounds__(256, 2) void attn_mma_kernel(float* __restrict__ out) {
    extern __shared__ float sm[];
    float* kbuf[2] = { sm, sm + 2560 };                       // 64 x 40 each
    float* vbuf[2] = { sm + 5120, sm + 5120 + 2304 };         // 64 x 36 each
    float* p_s = sm + 5120 + 4608;                            // 8 x 16 x 36

    const int qb = blockIdx.x;        // 0 or 1
    const int b  = blockIdx.y;
    const int tid = threadIdx.x, w = tid >> 5, lane = tid & 31;
    const int gq = lane >> 2, tg = lane & 3;
    const int nj = (qb + 1) * 4;

    const float* __restrict__ kg = g_kT + (size_t)b * 16384;
    const float* __restrict__ vg = g_vT + (size_t)b * 16384;

    const int rowg = qb * 128 + gq * 8 + w;
    const int row2 = rowg + 64;

    // Q fragments: frag-major, fully coalesced (8 float4 per lane)
    unsigned qa[8][4];
    {
        const float* __restrict__ qf =
            g_qF + (((size_t)b * 2 + qb) * 8 + w) * 1024 + (size_t)lane * 32;
#pragma unroll
        for (int kk = 0; kk < 8; kk++) {
            float4 t = *(const float4*)(qf + kk * 4);
            qa[kk][0] = __float_as_uint(t.x);
            qa[kk][1] = __float_as_uint(t.y);
            qa[kk][2] = __float_as_uint(t.z);
            qa[kk][3] = __float_as_uint(t.w);
        }
    }

    float o[8][4];
#pragma unroll
    for (int n = 0; n < 8; n++)
#pragma unroll
        for (int i = 0; i < 4; i++) o[n][i] = 0.0f;
    float m0 = -1e30f, m1 = -1e30f, l0 = 0.0f, l1 = 0.0f;

    float* pw = p_s + w * 576;
    const float* __restrict__ bfw =
        g_biasF + ((size_t)(qb * 4 * 8 + w) * 32 + lane) * 16;   // tile ti = qb*4 + jt

    // Prologue: stage tile 0 into buffer 0
    for (int f = tid; f < 512; f += 256) {
        int h = f >> 3, c4 = (f & 7) * 4;
        CP_ASYNC16(smaddr(kbuf[0] + h * KS + c4), kg + h * 256 + c4);
        CP_ASYNC16(smaddr(vbuf[0] + h * VS + c4), vg + h * 256 + c4);
    }
    CP_COMMIT();

    int buf = 0;
    for (int jt = 0; jt < nj; jt++) {
        const int j0 = jt * 32;
        asm volatile("cp.async.wait_group 0;");
        __syncthreads();

        if (jt + 1 < nj) {
            const int jn = j0 + 32;
            float* kn = kbuf[buf ^ 1];
            float* vn = vbuf[buf ^ 1];
            for (int f = tid; f < 512; f += 256) {
                int h = f >> 3, c4 = (f & 7) * 4;
                CP_ASYNC16(smaddr(kn + h * KS + c4), kg + h * 256 + jn + c4);
                CP_ASYNC16(smaddr(vn + h * VS + c4), vg + h * 256 + jn + c4);
            }
            CP_COMMIT();
        }

        const float* kb = kbuf[buf];
        const float* vb = vbuf[buf];

        // S = Q K^T  (q pre-scaled)
        float s[4][4];
#pragma unroll
        for (int n = 0; n < 4; n++)
#pragma unroll
            for (int i = 0; i < 4; i++) s[n][i] = 0.0f;
#pragma unroll
        for (int kk = 0; kk < 8; kk++) {
            const float* kb2 = kb + (kk * 8 + tg) * KS + gq;
#pragma unroll
            for (int nt = 0; nt < 4; nt++) {
                unsigned b0 = __float_as_uint(kb2[nt * 8]);
                unsigned b1 = __float_as_uint(kb2[4 * KS + nt * 8]);
                mma_tf32(s[nt], qa[kk], b0, b1);
            }
        }

        // + bias (frag-major float4, coalesced), causal mask
        const float* __restrict__ bft = bfw + (size_t)jt * 8 * 32 * 16;
#pragma unroll
        for (int nt = 0; nt < 4; nt++) {
            int c = nt * 8 + 2 * tg;
            int col = j0 + c;
            float4 bv = *(const float4*)(bft + nt * 4);
            s[nt][0] = (col     <= rowg) ? (s[nt][0] + bv.x) : -1e30f;
            s[nt][1] = (col + 1 <= rowg) ? (s[nt][1] + bv.y) : -1e30f;
            s[nt][2] = (col     <= row2) ? (s[nt][2] + bv.z) : -1e30f;
            s[nt][3] = (col + 1 <= row2) ? (s[nt][3] + bv.w) : -1e30f;
        }

        // online softmax
        float mx0 = -1e30f, mx1 = -1e30f;
#pragma unroll
        for (int nt = 0; nt < 4; nt++) {
            mx0 = fmaxf(mx0, fmaxf(s[nt][0], s[nt][1]));
            mx1 = fmaxf(mx1, fmaxf(s[nt][2], s[nt][3]));
        }
        mx0 = fmaxf(mx0, __shfl_xor_sync(0xffffffffu, mx0, 1));
        mx0 = fmaxf(mx0, __shfl_xor_sync(0xffffffffu, mx0, 2));
        mx1 = fmaxf(mx1, __shfl_xor_sync(0xffffffffu, mx1, 1));
        mx1 = fmaxf(mx1, __shfl_xor_sync(0xffffffffu, mx1, 2));
        float mn0 = fmaxf(m0, mx0), mn1 = fmaxf(m1, mx1);
        float al0 = __expf(m0 - mn0), al1 = __expf(m1 - mn1);
        m0 = mn0; m1 = mn1;

        float sum0 = 0.0f, sum1 = 0.0f;
        float e[4][4];
#pragma unroll
        for (int nt = 0; nt < 4; nt++) {
            e[nt][0] = __expf(s[nt][0] - mn0);
            e[nt][1] = __expf(s[nt][1] - mn0);
            e[nt][2] = __expf(s[nt][2] - mn1);
            e[nt][3] = __expf(s[nt][3] - mn1);
            sum0 += e[nt][0] + e[nt][1];
            sum1 += e[nt][2] + e[nt][3];
        }
        sum0 += __shfl_xor_sync(0xffffffffu, sum0, 1);
        sum0 += __shfl_xor_sync(0xffffffffu, sum0, 2);
        sum1 += __shfl_xor_sync(0xffffffffu, sum1, 1);
        sum1 += __shfl_xor_sync(0xffffffffu, sum1, 2);
        l0 = l0 * al0 + sum0;
        l1 = l1 * al1 + sum1;

#pragma unroll
        for (int nt = 0; nt < 8; nt++) {
            o[nt][0] *= al0; o[nt][1] *= al0;
            o[nt][2] *= al1; o[nt][3] *= al1;
        }

        // stage P (tf32) per-warp, stride 36
#pragma unroll
        for (int nt = 0; nt < 4; nt++) {
            int c = nt * 8 + 2 * tg;
            *(float2*)(pw + gq * PS + c) =
                make_float2(f2tff(e[nt][0]), f2tff(e[nt][1]));
            *(float2*)(pw + (gq + 8) * PS + c) =
                make_float2(f2tff(e[nt][2]), f2tff(e[nt][3]));
        }
        __syncwarp();

        // O += P V
#pragma unroll
        for (int ks = 0; ks < 4; ks++) {
            unsigned pa[4];
            pa[0] = __float_as_uint(pw[gq * PS + ks * 8 + tg]);
            pa[1] = __float_as_uint(pw[(gq + 8) * PS + ks * 8 + tg]);
            pa[2] = __float_as_uint(pw[gq * PS + ks * 8 + tg + 4]);
            pa[3] = __float_as_uint(pw[(gq + 8) * PS + ks * 8 + tg + 4]);
#pragma unroll
            for (int nt = 0; nt < 8; nt++) {
                const float* vb2 = vb + (nt * 8 + gq) * VS + ks * 8 + tg;
                unsigned b0 = __float_as_uint(vb2[0]);
                unsigned b1 = __float_as_uint(vb2[4]);
                mma_tf32(o[nt], pa, b0, b1);
            }
        }
        __syncwarp();

        __syncthreads();      // all warps done reading buf before restage
        buf ^= 1;
    }

    float inv0 = 1.0f / l0, inv1 = 1.0f / l1;
    float* ob = out + ((size_t)b * 256) * 64;
#pragma unroll
    for (int nt = 0; nt < 8; nt++) {
        int c = nt * 8 + 2 * tg;
        *(float2*)(ob + (size_t)rowg * 64 + c) =
            make_float2(o[nt][0] * inv0, o[nt][1] * inv0);
        *(float2*)(ob + (size_t)row2 * 64 + c) =
            make_float2(o[nt][2] * inv1, o[nt][3] * inv1);
    }
}

// ---------------------------------------------------------------------------
extern "C" void kernel_launch(void* const* d_in, const int* in_sizes, int n_in,
                              void* d_out, int out_size) {
    const float* x  = (const float*)d_in[0];
    const float* Wk = (const float*)d_in[1];
    const float* Wq = (const float*)d_in[2];
    const float* Wv = (const float*)d_in[3];
    const float* pe = (const float*)d_in[4];
    float* out = (float*)d_out;
    (void)in_sizes; (void)n_in; (void)out_size;

    static bool attr_set = false;
    if (!attr_set) {
        cudaFuncSetAttribute(qkv_mma_kernel,
                             cudaFuncAttributeMaxDynamicSharedMemorySize, 96256);
        cudaFuncSetAttribute(attn_mma_kernel,
                             cudaFuncAttributeMaxDynamicSharedMemorySize, 57344);
        attr_set = true;
    }

    qkv_mma_kernel<<<dim3(3, 512), 256, 96256>>>(x, Wq, Wk, Wv);
    pos_kernel<<<128, 256>>>(pe, Wk, Wq);
    bias_frag_kernel<<<12, dim3(32, 8)>>>();
    attn_mma_kernel<<<dim3(2, 512), 256, 57344>>>(out);
}